// round 13
// baseline (speedup 1.0000x reference)
#include <cuda_runtime.h>
#include <cstdint>
#include <cstddef>

// B=8192, I=H=O=4096. GEMM1+2 fused over K2=8192. Exact fixed-point (2^-20)
// via 3 balanced int8 limbs x ternary weights on s8 mma.sync (s32 accum).
// (tcgen05 is unusable: harness compiles PTX at .target sm_103, which rejects
//  tcgen05.ld/wait/dealloc — no TMEM readback path.)

__device__ __align__(256) int8_t g_A [3ULL * 8192 * 8192];   // limb planes [M][K2]
__device__ __align__(256) int8_t g_W [(size_t)4096 * 8192];  // [Wi|Wh] ternary [N][K2]
__device__ __align__(256) int8_t g_Wo[(size_t)4096 * 4096];  // Wo ternary [N][K]
__device__ __align__(256) int8_t g_Hq[(size_t)8192 * 4096];  // hidden_new ternary [M][K]
__device__ __align__(256) int    g_C [3ULL * 8192 * 4096];   // limb GEMM results, 3 planes

// ---------------- prep: weight ternarize + input limb decomposition ----------------
__global__ void k_prep(const float* __restrict__ x, const float* __restrict__ h,
                       const float* __restrict__ Wi, const float* __restrict__ Wh,
                       const float* __restrict__ Wo) {
    size_t idx = (size_t)blockIdx.x * blockDim.x + threadIdx.x;   // one float4
    const size_t WPER = (size_t)4096 * 4096 / 4;                  // 4194304
    const size_t APER = (size_t)8192 * 4096 / 4;                  // 8388608
    if (idx < 3 * WPER) {
        int w = (int)(idx / WPER);
        size_t e = idx % WPER;
        int row = (int)(e >> 10), c4 = (int)(e & 1023);
        const float4 v = reinterpret_cast<const float4*>(w == 0 ? Wi : (w == 1 ? Wh : Wo))[e];
        char4 q = make_char4(
            (int8_t)fminf(1.f, fmaxf(-1.f, rintf(v.x))),
            (int8_t)fminf(1.f, fmaxf(-1.f, rintf(v.y))),
            (int8_t)fminf(1.f, fmaxf(-1.f, rintf(v.z))),
            (int8_t)fminf(1.f, fmaxf(-1.f, rintf(v.w))));
        if (w == 0)      *reinterpret_cast<char4*>(&g_W [(size_t)row * 8192 + c4 * 4])        = q;
        else if (w == 1) *reinterpret_cast<char4*>(&g_W [(size_t)row * 8192 + 4096 + c4 * 4]) = q;
        else             *reinterpret_cast<char4*>(&g_Wo[(size_t)row * 4096 + c4 * 4])        = q;
    } else {
        size_t idx2 = idx - 3 * WPER;
        if (idx2 >= 2 * APER) return;
        int s = (int)(idx2 / APER);
        size_t e = idx2 % APER;
        int row = (int)(e >> 10), c4 = (int)(e & 1023);
        float4 v = reinterpret_cast<const float4*>(s ? h : x)[e];
        float f[4] = {v.x, v.y, v.z, v.w};
        signed char d0[4], d1[4], d2[4];
#pragma unroll
        for (int j = 0; j < 4; ++j) {
            float r = rintf(f[j] * 1048576.0f);               // x * 2^20, half-even
            r = fminf(8355711.0f, fmaxf(-8355711.0f, r));
            int t = (int)r;
            int e0 = ((t + 128) & 255) - 128; t = (t - e0) >> 8;
            int e1 = ((t + 128) & 255) - 128; t = (t - e1) >> 8;
            d0[j] = (signed char)e0; d1[j] = (signed char)e1; d2[j] = (signed char)t;
        }
        const size_t PLANE = (size_t)8192 * 8192;
        size_t off = (size_t)row * 8192 + (size_t)s * 4096 + (size_t)c4 * 4;
        *reinterpret_cast<char4*>(&g_A[off])             = make_char4(d0[0], d0[1], d0[2], d0[3]);
        *reinterpret_cast<char4*>(&g_A[PLANE + off])     = make_char4(d1[0], d1[1], d1[2], d1[3]);
        *reinterpret_cast<char4*>(&g_A[2 * PLANE + off]) = make_char4(d2[0], d2[1], d2[2], d2[3]);
    }
}

// -------- limb recombination (exact int64) + ternarize: writes hidden_new --------
__global__ void k_combine(float* __restrict__ outHid) {
    size_t idx = (size_t)blockIdx.x * blockDim.x + threadIdx.x;   // one int4
    const size_t N4 = (size_t)8192 * 4096 / 4;                    // 8388608
    if (idx >= N4) return;
    const int4* C = reinterpret_cast<const int4*>(g_C);
    int4 a = C[idx], b = C[idx + N4], c = C[idx + 2 * N4];
    int av[4] = {a.x, a.y, a.z, a.w};
    int bv[4] = {b.x, b.y, b.z, b.w};
    int cv[4] = {c.x, c.y, c.z, c.w};
    float o[4]; signed char hq[4];
#pragma unroll
    for (int j = 0; j < 4; ++j) {
        long long S = (long long)av[j] + 256LL * bv[j] + 65536LL * cv[j];  // pre*2^20 exact
        int hv = (S > 524288LL) ? 1 : ((S < -524288LL) ? -1 : 0);
        o[j] = (float)hv; hq[j] = (signed char)hv;
    }
    if (outHid) reinterpret_cast<float4*>(outHid)[idx] = make_float4(o[0], o[1], o[2], o[3]);
    *reinterpret_cast<char4*>(&g_Hq[idx * 4]) = make_char4(hq[0], hq[1], hq[2], hq[3]);
}

// ---------------- s8 mma.sync GEMM: C[M,N] (+)= A[M,K] * B[N,K]^T ----------------
// CTA 128x256, BK=128, 3-stage cp.async ring, 8 warps (2Mx4N), warp tile 64x64.
// SW128 XOR swizzle on 128B smem rows (conflict-free ldmatrix).
#define CP16(smaddr, gptr) \
    asm volatile("cp.async.cg.shared.global [%0], [%1], 16;" :: "r"(smaddr), "l"(gptr))
__device__ __forceinline__ uint32_t sw128(uint32_t off) { return off ^ ((off >> 3) & 0x70); }

template <int KDIM, bool OUTF>
__global__ __launch_bounds__(256, 1) void k_gemm(float* __restrict__ outF) {
    extern __shared__ int8_t dyn[];
    uint32_t sb = ((uint32_t)__cvta_generic_to_shared(dyn) + 1023u) & ~1023u;
    constexpr int AST = 128 * 128;          // A bytes per stage
    constexpr int BST = 256 * 128;          // B bytes per stage
    const uint32_t aS = sb, bS = sb + 3 * AST;

    const int bn = blockIdx.x, bm = blockIdx.y, z = blockIdx.z;
    const size_t APLANE = (size_t)8192 * 8192;
    const size_t CPLANE = (size_t)8192 * 4096;
    const int8_t* A  = (OUTF ? g_Hq : g_A + (size_t)z * APLANE) + (size_t)bm * 128 * KDIM;
    const int8_t* Bp = (OUTF ? g_Wo : g_W) + (size_t)bn * 256 * KDIM;

    const int tid = threadIdx.x, warp = tid >> 5, lane = tid & 31;
    const int wm = (warp & 1) * 64;         // warp M origin
    const int wn = (warp >> 1) * 64;        // warp N origin

    int c[4][8][4];
#pragma unroll
    for (int mt = 0; mt < 4; ++mt)
#pragma unroll
        for (int nt = 0; nt < 8; ++nt)
#pragma unroll
            for (int k = 0; k < 4; ++k) c[mt][nt][k] = 0;

    // stage fill: 384 rows x 8 chunks(16B) = 3072 chunks, 12 per thread
    auto LOAD = [&](int it, int s) {
        uint32_t aBase = aS + s * AST, bBase = bS + s * BST;
#pragma unroll
        for (int i0 = 0; i0 < 12; ++i0) {
            int i = i0 * 256 + tid;
            int row = i >> 3, c16 = (i & 7) * 16;
            if (row < 128) {
                const int8_t* src = A + (size_t)row * KDIM + it * 128 + c16;
                CP16(aBase + sw128((uint32_t)(row * 128 + c16)), src);
            } else {
                int r = row - 128;
                const int8_t* src = Bp + (size_t)r * KDIM + it * 128 + c16;
                CP16(bBase + sw128((uint32_t)(r * 128 + c16)), src);
            }
        }
    };

    const int NIT = KDIM / 128;
    LOAD(0, 0); asm volatile("cp.async.commit_group;");
    LOAD(1, 1); asm volatile("cp.async.commit_group;");

    for (int it = 0; it < NIT; ++it) {
        const int s = it % 3;
        asm volatile("cp.async.wait_group 1;");
        __syncthreads();
        const uint32_t aBase = aS + s * AST, bBase = bS + s * BST;

#pragma unroll
        for (int ks = 0; ks < 4; ++ks) {
            int afr[4][4], bfr[8][2];
            // A: matrices {m8lo k0-15, m8hi k0-15, m8lo k16-31, m8hi k16-31}
            const int arow = (lane & 7) + ((lane >> 3) & 1) * 8;
            const int akb  = ks * 32 + ((lane >> 4) & 1) * 16;
#pragma unroll
            for (int mt = 0; mt < 4; ++mt) {
                uint32_t ad = aBase + sw128((uint32_t)((wm + mt * 16 + arow) * 128 + akb));
                asm volatile("ldmatrix.sync.aligned.m8n8.x4.shared.b16 {%0,%1,%2,%3}, [%4];"
                             : "=r"(afr[mt][0]), "=r"(afr[mt][1]),
                               "=r"(afr[mt][2]), "=r"(afr[mt][3]) : "r"(ad));
            }
            // B: per np (pair of n8 tiles): {t0 k0-15, t0 k16-31, t1 k0-15, t1 k16-31}
            const int g = lane >> 3;
            const int brow = (g >> 1) * 8 + (lane & 7);
            const int bkb  = ks * 32 + (g & 1) * 16;
#pragma unroll
            for (int np = 0; np < 4; ++np) {
                uint32_t bd = bBase + sw128((uint32_t)((wn + np * 16 + brow) * 128 + bkb));
                asm volatile("ldmatrix.sync.aligned.m8n8.x4.shared.b16 {%0,%1,%2,%3}, [%4];"
                             : "=r"(bfr[np * 2][0]), "=r"(bfr[np * 2][1]),
                               "=r"(bfr[np * 2 + 1][0]), "=r"(bfr[np * 2 + 1][1]) : "r"(bd));
            }
#pragma unroll
            for (int mt = 0; mt < 4; ++mt)
#pragma unroll
                for (int nt = 0; nt < 8; ++nt) {
                    asm volatile(
                        "mma.sync.aligned.m16n8k32.row.col.s32.s8.s8.s32 "
                        "{%0,%1,%2,%3}, {%4,%5,%6,%7}, {%8,%9}, {%0,%1,%2,%3};"
                        : "+r"(c[mt][nt][0]), "+r"(c[mt][nt][1]),
                          "+r"(c[mt][nt][2]), "+r"(c[mt][nt][3])
                        : "r"(afr[mt][0]), "r"(afr[mt][1]), "r"(afr[mt][2]), "r"(afr[mt][3]),
                          "r"(bfr[nt][0]), "r"(bfr[nt][1]));
                }
        }
        __syncthreads();
        if (it + 2 < NIT) LOAD(it + 2, (it + 2) % 3);
        asm volatile("cp.async.commit_group;");
    }

    // epilogue
    const int gr = lane >> 2, gc = (lane & 3) * 2;
#pragma unroll
    for (int mt = 0; mt < 4; ++mt) {
#pragma unroll
        for (int nt = 0; nt < 8; ++nt) {
            const int row = bm * 128 + wm + mt * 16 + gr;
            const int col = bn * 256 + wn + nt * 8 + gc;
            if (OUTF) {
                *reinterpret_cast<float2*>(outF + (size_t)row * 4096 + col) =
                    make_float2((float)c[mt][nt][0], (float)c[mt][nt][1]);   // exact: |c|<=4096
                *reinterpret_cast<float2*>(outF + (size_t)(row + 8) * 4096 + col) =
                    make_float2((float)c[mt][nt][2], (float)c[mt][nt][3]);
            } else {
                int* Cz = g_C + (size_t)z * CPLANE;
                *reinterpret_cast<int2*>(Cz + (size_t)row * 4096 + col) =
                    make_int2(c[mt][nt][0], c[mt][nt][1]);
                *reinterpret_cast<int2*>(Cz + (size_t)(row + 8) * 4096 + col) =
                    make_int2(c[mt][nt][2], c[mt][nt][3]);
            }
        }
    }
}

// ---------------- launch ----------------
extern "C" void kernel_launch(void* const* d_in, const int* in_sizes, int n_in,
                              void* d_out, int out_size) {
    const float* x      = (const float*)d_in[0];
    const float* hidden = (const float*)d_in[1];
    const float* Wi     = (const float*)d_in[2];
    const float* Wh     = (const float*)d_in[3];
    const float* Wo     = (const float*)d_in[4];
    float* out = (float*)d_out;
    float* outHid = (out_size >= 67108864) ? (out + (size_t)33554432) : nullptr;

    constexpr int SMEM = 3 * (128 * 128 + 256 * 128) + 1024;   // 148480 B
    cudaFuncSetAttribute(k_gemm<8192, false>,
                         cudaFuncAttributeMaxDynamicSharedMemorySize, SMEM);
    cudaFuncSetAttribute(k_gemm<4096, true>,
                         cudaFuncAttributeMaxDynamicSharedMemorySize, SMEM);

    k_prep<<<114688, 256>>>(x, hidden, Wi, Wh, Wo);
    k_gemm<8192, false><<<dim3(16, 64, 3), 256, SMEM>>>(nullptr);   // limb planes -> g_C
    k_combine<<<32768, 256>>>(outHid);                              // pre -> hidden_new
    k_gemm<4096, true ><<<dim3(16, 64, 1), 256, SMEM>>>(out);       // output (exact int)
}